// round 15
// baseline (speedup 1.0000x reference)
#include <cuda_runtime.h>
#include <cstdint>

// GPT2Editor: softmax over a size-1 axis -> weights == 1, so
// out[s, :] = sum_f ( (h_last @ Wc[f][:, E:2E] + bc[f][E:]) @ Wp[f] + bp[f] )
// broadcast to all 4096 rows. Dead inputs: encoder_hidden_states, Wq, bq.
// E = 2048, F = 4.
//
// r15: uniform produce-then-consume blocks. Each of 1024 worker blocks
// (1) computes one 8-wide v segment (64KB of Wc), releases a flag,
// (2) immediately consumes a 16-row Wp chunk gated on its own neighbor
//     pair of flags (ready ~instantly), streaming another 64KB.
// Both phases therefore run at full ~55 warps/SM occupancy -- no more
// half-idle producer/consumer split. Reduce stays in-kernel (64 blocks),
// broadcast is the empirically-floored minimal-STG kernel (8.4us).

#define EDIM 2048
#define FDIM 4
#define SOUT 4096
#define NSEG 256                      // 8-wide v segments per f
#define NWORK 1024                    // worker blocks (produce + consume)
#define NRBLK 64                      // reducer blocks

__device__ float g_v[FDIM * EDIM];        // complete v rows (bc included)
__device__ float g_part_r[512 * EDIM];    // r partials per (f, cr16)
__device__ float g_r[EDIM];               // final broadcast row
__device__ int   g_flag[NWORK];           // v-segment ready flags
__device__ int   g_cnt;                   // consumer-done counter

__global__ void __launch_bounds__(256)
fused_vr_kernel(const float* __restrict__ h_last,
                const float* __restrict__ Wc,
                const float* __restrict__ bc,
                const float* __restrict__ Wp,
                const float* __restrict__ bp) {
    __shared__ float sh[EDIM];          // h_last copy (producer phase)
    __shared__ float4 red[128][2];      // producer reduction tree
    __shared__ float sv[16];            // v chunk (consumer phase)

    const int bid = blockIdx.x;
    const int t   = threadIdx.x;

    if (bid < NWORK) {
        // ── Phase P: produce v[f, g*8 .. g*8+7]  (f = bid>>8, g = bid&255)
        const int f  = bid >> 8;
        const int g  = bid & 255;
        const int j0 = g * 8;
        const int q  = t & 1;            // which float4 of the 8-wide segment
        const int s  = t >> 1;           // e-strip 0..127

        const float4* h4 = reinterpret_cast<const float4*>(h_last);
        reinterpret_cast<float4*>(sh)[t]       = h4[t];
        reinterpret_cast<float4*>(sh)[t + 256] = h4[t + 256];
        __syncthreads();

        const float* W = Wc + (size_t)f * EDIM * (2 * EDIM) + EDIM + j0 + q * 4;
        float4 acc = make_float4(0.f, 0.f, 0.f, 0.f);
#pragma unroll
        for (int k = 0; k < 16; k++) {
            const int e = k * 128 + s;
            float4 w = __ldcs(reinterpret_cast<const float4*>(W + (size_t)e * (2 * EDIM)));
            float hv = sh[e];
            acc.x = fmaf(hv, w.x, acc.x);
            acc.y = fmaf(hv, w.y, acc.y);
            acc.z = fmaf(hv, w.z, acc.z);
            acc.w = fmaf(hv, w.w, acc.w);
        }
        red[s][q] = acc;
        __syncthreads();
        if (t < 32) {                    // s<16, both q
            float4 r2 = red[s][q];
#pragma unroll
            for (int m = 1; m < 8; m++) {
                float4 o = red[s + 16 * m][q];
                r2.x += o.x; r2.y += o.y; r2.z += o.z; r2.w += o.w;
            }
            red[s][q] = r2;
        }
        __syncthreads();
        if (t < 2) {                     // q = t
            float4 r3 = red[0][t];
#pragma unroll
            for (int i = 1; i < 16; i++) {
                float4 o = red[i][t];
                r3.x += o.x; r3.y += o.y; r3.z += o.z; r3.w += o.w;
            }
            float4 b4 = *reinterpret_cast<const float4*>(
                bc + (size_t)f * 2 * EDIM + EDIM + j0 + t * 4);
            r3.x += b4.x; r3.y += b4.y; r3.z += b4.z; r3.w += b4.w;
            *reinterpret_cast<float4*>(&g_v[f * EDIM + j0 + t * 4]) = r3;
            __threadfence();
        }
        __syncthreads();
        if (t == 0) {
            asm volatile("st.release.gpu.s32 [%0], %1;"
                         :: "l"(&g_flag[bid]), "r"(1) : "memory");
        }

        // ── Phase C: consume chunk (f, cr, x) where cr = (bid&255)>>1,
        //    x = bid&1. Needs segments 2cr, 2cr+1 = flags bid&~1, bid|1
        //    (one is our own, the neighbor finishes ~simultaneously).
        const int cr = g >> 1;
        const int x  = bid & 1;
        const int e0 = cr * 16;

        if (t == 0) {
            int rdy;
            const int fl0 = bid & ~1;
            while (true) {
                asm volatile("ld.acquire.gpu.s32 %0, [%1];"
                             : "=r"(rdy) : "l"(&g_flag[fl0]) : "memory");
                if (rdy) break;
                __nanosleep(64);
            }
            while (true) {
                asm volatile("ld.acquire.gpu.s32 %0, [%1];"
                             : "=r"(rdy) : "l"(&g_flag[fl0 + 1]) : "memory");
                if (rdy) break;
                __nanosleep(64);
            }
        }
        __syncthreads();
        if (t < 16) sv[t] = g_v[f * EDIM + e0 + t];
        __syncthreads();

        const int j = x * 1024 + t * 4;
        const float* Wr = Wp + ((size_t)f * EDIM + e0) * EDIM + j;
        float4 acc2 = make_float4(0.f, 0.f, 0.f, 0.f);
#pragma unroll
        for (int e = 0; e < 16; e++) {
            float4 w = __ldcs(reinterpret_cast<const float4*>(Wr + (size_t)e * EDIM));
            float vv = sv[e];
            acc2.x = fmaf(vv, w.x, acc2.x);
            acc2.y = fmaf(vv, w.y, acc2.y);
            acc2.z = fmaf(vv, w.z, acc2.z);
            acc2.w = fmaf(vv, w.w, acc2.w);
        }
        *reinterpret_cast<float4*>(
            &g_part_r[((size_t)f * 128 + cr) * EDIM + j]) = acc2;

        __syncthreads();
        if (t == 0) {
            __threadfence();
            atomicAdd(&g_cnt, 1);
        }
    } else {
        // ── Reducer rb: wait for all 1024 workers, then
        //    g_r[o] = sum of 512 part_r rows + sum_f bp[f,o]
        __shared__ float red2[8][32];
        const int rb = bid - NWORK;      // 0..63

        if (t == 0) {
            int d;
            do {
                asm volatile("ld.acquire.gpu.s32 %0, [%1];"
                             : "=r"(d) : "l"(&g_cnt) : "memory");
                if (d < NWORK) __nanosleep(256);
            } while (d < NWORK);
        }
        __syncthreads();

        const int p = t >> 5;            // 0..7
        const int o = rb * 32 + (t & 31);
        float s = 0.0f;
#pragma unroll
        for (int k = 0; k < 64; k++)
            s += g_part_r[((size_t)p + 8 * k) * EDIM + o];
        red2[p][t & 31] = s;
        __syncthreads();
        if (t < 32) {
            int oo = rb * 32 + t;
            float a = 0.0f;
#pragma unroll
            for (int f = 0; f < FDIM; f++) a += bp[(size_t)f * EDIM + oo];
#pragma unroll
            for (int i = 0; i < 8; i++) a += red2[i][t];
            g_r[oo] = a;
        }
    }
}

// out[s, :] = r[:], one row per block, minimal-STG form (~8.4us measured
// floor). Block 0 also resets sync state for the next graph replay.
__global__ void __launch_bounds__(256)
bcast_kernel(float4* __restrict__ out) {
    if (blockIdx.x == 0) {
        g_flag[threadIdx.x]       = 0;
        g_flag[threadIdx.x + 256] = 0;
        g_flag[threadIdx.x + 512] = 0;
        g_flag[threadIdx.x + 768] = 0;
        if (threadIdx.x == 0) g_cnt = 0;
    }
    const float4* r4 = reinterpret_cast<const float4*>(g_r);
    const size_t s = blockIdx.x;
    float4 a = r4[threadIdx.x];
    float4 b = r4[threadIdx.x + 256];
    out[s * 512 + threadIdx.x]       = a;
    out[s * 512 + threadIdx.x + 256] = b;
}

extern "C" void kernel_launch(void* const* d_in, const int* in_sizes, int n_in,
                              void* d_out, int out_size) {
    // order: hidden_states, encoder_hidden_states, Wq, bq, Wc, bc, Wp, bp
    const float* hidden = (const float*)d_in[0];
    const float* Wc     = (const float*)d_in[4];
    const float* bc     = (const float*)d_in[5];
    const float* Wp     = (const float*)d_in[6];
    const float* bp     = (const float*)d_in[7];
    float* out = (float*)d_out;

    const float* h_last = hidden + 127 * EDIM;  // hidden_states[0, -1, :]

    fused_vr_kernel<<<NWORK + NRBLK, 256>>>(h_last, Wc, bc, Wp, bp);
    bcast_kernel<<<SOUT, 256>>>((float4*)out);
}

// round 16
// speedup vs baseline: 1.3744x; 1.3744x over previous
#include <cuda_runtime.h>
#include <cstdint>

// GPT2Editor: softmax over a size-1 axis -> weights == 1, so
// out[s, :] = sum_f ( (h_last @ Wc[f][:, E:2E] + bc[f][E:]) @ Wp[f] + bp[f] )
// broadcast to all 4096 rows. Dead inputs: encoder_hidden_states, Wq, bq.
// E = 2048, F = 4.
//
// r16: compose the measured-best components.
//  1) fused_vr: r12's exact producer/consumer kernel (measured ~24.8us,
//     at the overlapped-streaming floor). 512 producers (16-wide v
//     segments, flag release) + 512 consumers (Wp chunks), all resident.
//  2) reduce_r: standalone 64-block partial reduction (~1.5-2us, L2-hot).
//  3) bcast: minimal-STG broadcast (measured 8.4us floor across 7 shapes).

#define EDIM 2048
#define FDIM 4
#define SOUT 4096
#define NGRP 128                      // 16-wide v segments per f
#define NVBLK (FDIM * NGRP)           // 512 producer blocks
#define NCBLK 512                     // consumer blocks (f x cr)

__device__ float g_v[FDIM * EDIM];        // complete v rows (bc included)
__device__ float g_part_r[NCBLK * EDIM];  // r partials per (f, cr)
__device__ float g_r[EDIM];               // final broadcast row
__device__ int   g_flag[NVBLK];           // v-segment ready flags

__global__ void __launch_bounds__(256)
fused_vr_kernel(const float* __restrict__ h_last,
                const float* __restrict__ Wc,
                const float* __restrict__ bc,
                const float* __restrict__ Wp) {
    const int bid = blockIdx.x;
    const int t   = threadIdx.x;

    if (bid < NVBLK) {
        // ── Producer: v[f, j0..j0+15] = bc + sum_e h[e] * Wc[f, e, E+j0..]
        __shared__ float sh[EDIM];
        __shared__ float4 red[64][4];

        const float4* h4 = reinterpret_cast<const float4*>(h_last);
        reinterpret_cast<float4*>(sh)[t]       = h4[t];
        reinterpret_cast<float4*>(sh)[t + 256] = h4[t + 256];
        __syncthreads();

        const int f  = bid >> 7;        // 0..3
        const int g  = bid & 127;       // 0..127
        const int j0 = g * 16;
        const int q  = t & 3;           // j-quad within segment
        const int s  = t >> 2;          // e-strip 0..63

        const float* W = Wc + (size_t)f * EDIM * (2 * EDIM) + EDIM + j0 + q * 4;
        float4 acc = make_float4(0.f, 0.f, 0.f, 0.f);
#pragma unroll
        for (int k = 0; k < 32; k++) {
            const int e = k * 64 + s;
            float4 w = __ldcs(reinterpret_cast<const float4*>(W + (size_t)e * (2 * EDIM)));
            float hv = sh[e];
            acc.x = fmaf(hv, w.x, acc.x);
            acc.y = fmaf(hv, w.y, acc.y);
            acc.z = fmaf(hv, w.z, acc.z);
            acc.w = fmaf(hv, w.w, acc.w);
        }
        red[s][q] = acc;
        __syncthreads();
        if (s < 8) {
            float4 r2 = red[s][q];
#pragma unroll
            for (int m = 1; m < 8; m++) {
                float4 o = red[s + 8 * m][q];
                r2.x += o.x; r2.y += o.y; r2.z += o.z; r2.w += o.w;
            }
            red[s][q] = r2;
        }
        __syncthreads();
        if (t < 4) {   // s==0, q==t
            float4 r3 = red[0][t];
#pragma unroll
            for (int i = 1; i < 8; i++) {
                float4 o = red[i][t];
                r3.x += o.x; r3.y += o.y; r3.z += o.z; r3.w += o.w;
            }
            float4 b4 = *reinterpret_cast<const float4*>(
                bc + (size_t)f * 2 * EDIM + EDIM + j0 + t * 4);
            r3.x += b4.x; r3.y += b4.y; r3.z += b4.z; r3.w += b4.w;
            *reinterpret_cast<float4*>(&g_v[f * EDIM + j0 + t * 4]) = r3;
            __threadfence();
        }
        __syncthreads();
        if (t == 0) {
            asm volatile("st.release.gpu.s32 [%0], %1;"
                         :: "l"(&g_flag[bid]), "r"(1) : "memory");
        }
    } else {
        // ── Consumer (f, cr), both x-halves:
        //    part_r[f][cr][j..j+3] = sum_{e in 16-chunk} v[f,e] * Wp[f,e,j..]
        __shared__ float sv[16];
        const int b2 = bid - NVBLK;     // 0..511
        const int f  = b2 >> 7;         // 0..3
        const int cr = b2 & 127;        // 0..127
        const int e0 = cr * 16;

        if (t == 0) {
            int rdy;
            while (true) {
                asm volatile("ld.acquire.gpu.s32 %0, [%1];"
                             : "=r"(rdy) : "l"(&g_flag[f * NGRP + cr]) : "memory");
                if (rdy) break;
                __nanosleep(128);
            }
        }
        __syncthreads();
        if (t < 16) sv[t] = g_v[f * EDIM + e0 + t];
        __syncthreads();

        const int j = t * 4;
        const float* W = Wp + ((size_t)f * EDIM + e0) * EDIM + j;
        float4 acc0 = make_float4(0.f, 0.f, 0.f, 0.f);
        float4 acc1 = make_float4(0.f, 0.f, 0.f, 0.f);
#pragma unroll
        for (int e = 0; e < 16; e++) {
            float4 w0 = __ldcs(reinterpret_cast<const float4*>(W + (size_t)e * EDIM));
            float4 w1 = __ldcs(reinterpret_cast<const float4*>(W + (size_t)e * EDIM + 1024));
            float vv = sv[e];
            acc0.x = fmaf(vv, w0.x, acc0.x);
            acc0.y = fmaf(vv, w0.y, acc0.y);
            acc0.z = fmaf(vv, w0.z, acc0.z);
            acc0.w = fmaf(vv, w0.w, acc0.w);
            acc1.x = fmaf(vv, w1.x, acc1.x);
            acc1.y = fmaf(vv, w1.y, acc1.y);
            acc1.z = fmaf(vv, w1.z, acc1.z);
            acc1.w = fmaf(vv, w1.w, acc1.w);
        }
        float* dst = &g_part_r[((size_t)f * NGRP + cr) * EDIM + j];
        *reinterpret_cast<float4*>(dst)        = acc0;
        *reinterpret_cast<float4*>(dst + 1024) = acc1;
    }
}

// g_r[o] = sum over 512 part_r partials + sum_f bp[f,o].
// 64 blocks; part_r is L2-hot. Runs after fused_vr via kernel boundary.
__global__ void __launch_bounds__(256)
reduce_r_kernel(const float* __restrict__ bp) {
    __shared__ float red[8][32];
    const int t = threadIdx.x;
    const int p = t >> 5;
    const int o = blockIdx.x * 32 + (t & 31);

    float s = 0.0f;
#pragma unroll
    for (int k = 0; k < 64; k++)
        s += g_part_r[((size_t)p + 8 * k) * EDIM + o];
    red[p][t & 31] = s;
    __syncthreads();

    if (t < 32) {
        int oo = blockIdx.x * 32 + t;
        float a = 0.0f;
#pragma unroll
        for (int f = 0; f < FDIM; f++) a += bp[(size_t)f * EDIM + oo];
#pragma unroll
        for (int i = 0; i < 8; i++) a += red[i][t];
        g_r[oo] = a;
    }
}

// out[s, :] = r[:], one row per block, minimal-STG form (measured ~8.4us
// floor). Block 0 resets flags for the next graph replay (their waiters
// all finished two kernels ago).
__global__ void __launch_bounds__(256)
bcast_kernel(float4* __restrict__ out) {
    if (blockIdx.x == 0) {
        g_flag[threadIdx.x]       = 0;
        g_flag[threadIdx.x + 256] = 0;
    }
    const float4* r4 = reinterpret_cast<const float4*>(g_r);
    const size_t s = blockIdx.x;
    float4 a = r4[threadIdx.x];
    float4 b = r4[threadIdx.x + 256];
    out[s * 512 + threadIdx.x]       = a;
    out[s * 512 + threadIdx.x + 256] = b;
}

extern "C" void kernel_launch(void* const* d_in, const int* in_sizes, int n_in,
                              void* d_out, int out_size) {
    // order: hidden_states, encoder_hidden_states, Wq, bq, Wc, bc, Wp, bp
    const float* hidden = (const float*)d_in[0];
    const float* Wc     = (const float*)d_in[4];
    const float* bc     = (const float*)d_in[5];
    const float* Wp     = (const float*)d_in[6];
    const float* bp     = (const float*)d_in[7];
    float* out = (float*)d_out;

    const float* h_last = hidden + 127 * EDIM;  // hidden_states[0, -1, :]

    fused_vr_kernel<<<NVBLK + NCBLK, 256>>>(h_last, Wc, bc, Wp);
    reduce_r_kernel<<<EDIM / 32, 256>>>(bp);
    bcast_kernel<<<SOUT, 256>>>((float4*)out);
}